// round 15
// baseline (speedup 1.0000x reference)
#include <cuda_runtime.h>
#include <cuda_fp16.h>
#include <math.h>
#include <stdint.h>

#define E_   1024
#define NH_  8
#define HD_  128
#define BS_  2048

// ---- scratch (device globals; no allocation allowed) ----
__device__ __half g_x1h[BS_ * E_];
__device__ __half g_x2h[BS_ * E_];
__device__ __half g_Wqh[E_ * E_];
__device__ __half g_Wkh[E_ * E_];
__device__ __half g_Wvh[E_ * E_];
__device__ __half g_Woh[E_ * E_];
__device__ __half g_W1h[4 * E_ * E_];
__device__ __half g_W2h[4 * E_ * E_];
__device__ __half g_Qh[BS_ * E_];
__device__ __half g_Kh[BS_ * E_];
__device__ __half g_Vh[BS_ * E_];
__device__ __half g_Vth[NH_ * HD_ * BS_];        // per-head transposed V (half)
__device__ __half g_Ph[(size_t)NH_ * BS_ * BS_]; // half scores -> probs (in place)
__device__ __half g_attnh[BS_ * E_];
__device__ float  g_h[BS_ * E_];
__device__ __half g_hh[BS_ * E_];
__device__ __half g_f1h[BS_ * 4 * E_];
__device__ float  g_part[2 * BS_ * E_];          // split-K partials

// ============================================================
// helpers
// ============================================================
__device__ __forceinline__ uint32_t smem_u32(const void* p) {
    uint32_t a;
    asm("{ .reg .u64 t; cvta.to.shared.u64 t, %1; cvt.u32.u64 %0, t; }" : "=r"(a) : "l"(p));
    return a;
}
__device__ __forceinline__ void cp16(uint32_t dst, const void* src) {
    asm volatile("cp.async.cg.shared.global [%0], [%1], 16;" :: "r"(dst), "l"(src));
}
#define CP_COMMIT() asm volatile("cp.async.commit_group;" ::: "memory")
#define CP_WAIT1()  asm volatile("cp.async.wait_group 1;" ::: "memory")

__device__ __forceinline__ void mma16(float c[4], uint32_t a0, uint32_t a1,
                                      uint32_t a2, uint32_t a3,
                                      uint32_t b0, uint32_t b1) {
    asm volatile(
        "mma.sync.aligned.m16n8k16.row.col.f32.f16.f16.f32 "
        "{%0,%1,%2,%3}, {%4,%5,%6,%7}, {%8,%9}, {%0,%1,%2,%3};"
        : "+f"(c[0]), "+f"(c[1]), "+f"(c[2]), "+f"(c[3])
        : "r"(a0), "r"(a1), "r"(a2), "r"(a3), "r"(b0), "r"(b1));
}
__device__ __forceinline__ void ldmx4(uint32_t& r0, uint32_t& r1, uint32_t& r2,
                                      uint32_t& r3, uint32_t addr) {
    asm volatile("ldmatrix.sync.aligned.m8n8.x4.shared.b16 {%0,%1,%2,%3}, [%4];"
                 : "=r"(r0), "=r"(r1), "=r"(r2), "=r"(r3) : "r"(addr));
}
__device__ __forceinline__ void ldmx2(uint32_t& r0, uint32_t& r1, uint32_t addr) {
    asm volatile("ldmatrix.sync.aligned.m8n8.x2.shared.b16 {%0,%1}, [%2];"
                 : "=r"(r0), "=r"(r1) : "r"(addr));
}

// ============================================================
// fused multi-tensor fp32 -> fp16 convert (8 segments, one launch)
// ============================================================
struct ConvSeg {
    const float* in[8];
    __half* out[8];
    unsigned cum[9];
};

__global__ __launch_bounds__(256) void to_half_multi(ConvSeg cs)
{
    const unsigned idx = blockIdx.x * 256 + threadIdx.x;
    if (idx >= cs.cum[8]) return;
    int s = 0;
#pragma unroll
    for (int i = 1; i < 8; ++i) s += (idx >= cs.cum[i]);
    const unsigned off = idx - cs.cum[s];
    float4 v = ((const float4*)cs.in[s])[off];
    __half2* o = (__half2*)cs.out[s] + (size_t)off * 2;
    o[0] = __floats2half2_rn(v.x, v.y);
    o[1] = __floats2half2_rn(v.z, v.w);
}

// ============================================================
// fp16 tensor-core NT GEMM core: C = A @ B^T (+bias), opt ReLU
// BM=BN=128, BK=64, 3-stage cp.async, single sync per BK=64,
// ldmatrix, 8 warps (2x4), warp tile 64x32, mma m16n8k16.
// ============================================================
#define SROWH 72                         // halves per smem row (64 + 8 pad)
#define STAGE_H (2 * 128 * SROWH)        // halves per stage (A+B)
#define GEMM_SMEM (3 * STAGE_H * 2)      // bytes (3 stages) = 110592

__device__ __forceinline__ void gemm_core(
    const __half* __restrict__ A, int lda,
    const __half* __restrict__ B, int ldb,
    const float* __restrict__ bias,
    float* __restrict__ Cf, __half* __restrict__ Ch, int ldc,
    int K, int relu, int koff, __half* smh)
{
    const int tid = threadIdx.x;
    const int bm = blockIdx.y * 128, bn = blockIdx.x * 128;

    // loader: one full 64-half row per thread. tid<128 -> A, else B.
    const int lrow = tid & 127;
    const int isB = tid >> 7;
    const __half* gR = (isB ? B + (size_t)(bn + lrow) * ldb
                            : A + (size_t)(bm + lrow) * lda) + koff;
    const uint32_t smbase = smem_u32(smh);
    const uint32_t dRow = smbase + (uint32_t)((isB * 128 + lrow) * SROWH) * 2u;

    const int warp = tid >> 5, lane = tid & 31;
    const int g = lane >> 2, tig = lane & 3;
    const int am = (warp >> 2) * 64;
    const int bnw = (warp & 3) * 32;

    const uint32_t aAddr0 = smbase +
        (uint32_t)(((am + (lane & 15)) * SROWH) + ((lane >> 4) << 3)) * 2u;
    const uint32_t bAddr0 = smbase + 128u * SROWH * 2u +
        (uint32_t)(((bnw + (lane & 7)) * SROWH) + (((lane >> 3) & 1) << 3)) * 2u;

    float acc[4][4][4];
#pragma unroll
    for (int mi = 0; mi < 4; ++mi)
#pragma unroll
        for (int ni = 0; ni < 4; ++ni)
#pragma unroll
            for (int r = 0; r < 4; ++r) acc[mi][ni][r] = 0.f;

    const int NT = K >> 6;   // BK = 64

    // prologue: stages 0,1
#pragma unroll
    for (int s = 0; s < 2; ++s) {
        const uint32_t d = dRow + (uint32_t)(s * STAGE_H) * 2u;
        const __half* p = gR + s * 64;
#pragma unroll
        for (int c = 0; c < 8; ++c) cp16(d + c * 16u, p + c * 8);
        CP_COMMIT();
    }

    for (int kt = 0; kt < NT; ++kt) {
        CP_WAIT1();
        __syncthreads();

        // refill stage (kt+2)%3 (overwrites kt-1; safe after sync)
        if (kt + 2 < NT) {
            const int s = (kt + 2) % 3;
            const uint32_t d = dRow + (uint32_t)(s * STAGE_H) * 2u;
            const __half* p = gR + (kt + 2) * 64;
#pragma unroll
            for (int c = 0; c < 8; ++c) cp16(d + c * 16u, p + c * 8);
        }
        CP_COMMIT();

        const uint32_t stOff = (uint32_t)((kt % 3) * STAGE_H) * 2u;

#pragma unroll
        for (int k16 = 0; k16 < 4; ++k16) {
            const uint32_t kOff = (uint32_t)(k16 * 16) * 2u;
            uint32_t a[4][4];
#pragma unroll
            for (int mi = 0; mi < 4; ++mi)
                ldmx4(a[mi][0], a[mi][1], a[mi][2], a[mi][3],
                      aAddr0 + stOff + kOff + (uint32_t)(mi * 16 * SROWH) * 2u);
            uint32_t b[4][2];
#pragma unroll
            for (int ni = 0; ni < 4; ++ni)
                ldmx2(b[ni][0], b[ni][1],
                      bAddr0 + stOff + kOff + (uint32_t)(ni * 8 * SROWH) * 2u);
#pragma unroll
            for (int mi = 0; mi < 4; ++mi)
#pragma unroll
                for (int ni = 0; ni < 4; ++ni)
                    mma16(acc[mi][ni], a[mi][0], a[mi][1], a[mi][2], a[mi][3],
                          b[ni][0], b[ni][1]);
        }
    }

#pragma unroll
    for (int mi = 0; mi < 4; ++mi) {
        const int r0 = bm + am + mi * 16 + g;
#pragma unroll
        for (int ni = 0; ni < 4; ++ni) {
            const int col = bn + bnw + ni * 8 + 2 * tig;
            const float bi0 = bias ? bias[col] : 0.f;
            const float bi1 = bias ? bias[col + 1] : 0.f;
            float v0 = acc[mi][ni][0] + bi0, v1 = acc[mi][ni][1] + bi1;
            float v2 = acc[mi][ni][2] + bi0, v3 = acc[mi][ni][3] + bi1;
            if (relu) {
                v0 = fmaxf(v0, 0.f); v1 = fmaxf(v1, 0.f);
                v2 = fmaxf(v2, 0.f); v3 = fmaxf(v3, 0.f);
            }
            if (Cf) {
                float2 p0 = {v0, v1}, p1 = {v2, v3};
                *(float2*)(Cf + (size_t)r0 * ldc + col) = p0;
                *(float2*)(Cf + (size_t)(r0 + 8) * ldc + col) = p1;
            }
            if (Ch) {
                *(__half2*)(Ch + (size_t)r0 * ldc + col) = __floats2half2_rn(v0, v1);
                *(__half2*)(Ch + (size_t)(r0 + 8) * ldc + col) = __floats2half2_rn(v2, v3);
            }
        }
    }
}

// generic wrapper with per-z plane offsets
__global__ __launch_bounds__(256, 2) void gemm_h(
    const __half* __restrict__ A, long long az, int lda,
    const __half* __restrict__ B, long long bz, int ldb,
    const float* __restrict__ bias,
    float* __restrict__ Cf, __half* __restrict__ Ch,
    long long cz, int ldc, int K, int relu)
{
    extern __shared__ __align__(16) __half smh[];
    const int z = blockIdx.z;
    gemm_core(A + (size_t)z * az, lda, B + (size_t)z * bz, ldb, bias,
              Cf ? Cf + (size_t)z * cz : nullptr,
              Ch ? Ch + (size_t)z * cz : nullptr,
              ldc, K, relu, 0, smh);
}

// merged QKV wrapper
struct QKVArgs {
    const __half* A[3];
    const __half* B[3];
    const float* bias[3];
    __half* C[3];
};
__global__ __launch_bounds__(256, 2) void gemm_qkv(QKVArgs q)
{
    extern __shared__ __align__(16) __half smh[];
    const int z = blockIdx.z;
    gemm_core(q.A[z], 1024, q.B[z], 1024, q.bias[z],
              nullptr, q.C[z], 1024, 1024, 0, 0, smh);
}

// attn split-K wrapper: z = head*2 + split. K=2048 split into 2x1024.
__global__ __launch_bounds__(256, 2) void gemm_attn_sk(
    const __half* __restrict__ P, const __half* __restrict__ Vt,
    float* __restrict__ part)
{
    extern __shared__ __align__(16) __half smh[];
    const int head = blockIdx.z >> 1, split = blockIdx.z & 1;
    gemm_core(P + ((size_t)head << 22), 2048,
              Vt + (size_t)head * 128 * 2048, 2048,
              nullptr,
              part + (size_t)split * (2048 * 1024) + head * 128, nullptr,
              1024, 1024, 0, split * 1024, smh);
}

// generic split-K=2 wrapper (N=1024, M=2048): z = split.
__global__ __launch_bounds__(256, 2) void gemm_sk(
    const __half* __restrict__ A, int lda,
    const __half* __restrict__ B, int ldb,
    float* __restrict__ part, int Ksplit)
{
    extern __shared__ __align__(16) __half smh[];
    const int split = blockIdx.z;
    gemm_core(A, lda, B, ldb, nullptr,
              part + (size_t)split * (2048 * 1024), nullptr,
              1024, Ksplit, 0, split * Ksplit, smh);
}

// ============================================================
// partial reduce: out_h = half(p0 + p1)
// ============================================================
__global__ __launch_bounds__(256) void add2half(
    const float* __restrict__ p0, const float* __restrict__ p1,
    __half* __restrict__ out)
{
    const size_t i = (size_t)blockIdx.x * 256 + threadIdx.x;
    float4 a = ((const float4*)p0)[i];
    float4 b = ((const float4*)p1)[i];
    __half2* o = (__half2*)out + i * 2;
    o[0] = __floats2half2_rn(a.x + b.x, a.y + b.y);
    o[1] = __floats2half2_rn(a.z + b.z, a.w + b.w);
}

// ============================================================
// V transpose (half): Vth[h][d][m] = Vh[m][h*128+d]. Grid (64,4,8)
// ============================================================
__global__ void vt_kernel(const __half* __restrict__ V, __half* __restrict__ Vt)
{
    __shared__ __half t[32][34];
    const int m0 = blockIdx.x * 32, d0 = blockIdx.y * 32, h = blockIdx.z;
    const int tx = threadIdx.x, ty = threadIdx.y;
#pragma unroll
    for (int j = 0; j < 32; j += 8)
        t[ty + j][tx] = V[(size_t)(m0 + ty + j) * 1024 + h * 128 + d0 + tx];
    __syncthreads();
    __half* dst = Vt + (size_t)h * 128 * 2048;
#pragma unroll
    for (int j = 0; j < 32; j += 8)
        dst[(size_t)(d0 + ty + j) * 2048 + m0 + tx] = t[tx][ty + j];
}

// ============================================================
// Softmax over the 8 head planes, in place on half scores.
// ============================================================
__global__ __launch_bounds__(256) void softmax8h(__half* __restrict__ P)
{
    const size_t idx = (size_t)blockIdx.x * 256 + threadIdx.x;
    const float scale = 0.08838834764831845f;  // 1/sqrt(128)
    const size_t planeh = (size_t)1 << 22;

    float v[8][4];
#pragma unroll
    for (int h = 0; h < 8; ++h) {
        const __half2* p = (const __half2*)(P + h * planeh) + idx * 2;
        float2 a = __half22float2(p[0]);
        float2 b = __half22float2(p[1]);
        v[h][0] = a.x; v[h][1] = a.y; v[h][2] = b.x; v[h][3] = b.y;
    }

#pragma unroll
    for (int lane = 0; lane < 4; ++lane) {
        float s[8], mx = -1e30f;
#pragma unroll
        for (int h = 0; h < 8; ++h) {
            s[h] = v[h][lane] * scale;
            mx = fmaxf(mx, s[h]);
        }
        float sum = 0.f;
#pragma unroll
        for (int h = 0; h < 8; ++h) { s[h] = expf(s[h] - mx); sum += s[h]; }
        const float inv = 1.0f / sum;
#pragma unroll
        for (int h = 0; h < 8; ++h) v[h][lane] = s[h] * inv;
    }

#pragma unroll
    for (int h = 0; h < 8; ++h) {
        __half2* p = (__half2*)(P + h * planeh) + idx * 2;
        p[0] = __floats2half2_rn(v[h][0], v[h][1]);
        p[1] = __floats2half2_rn(v[h][2], v[h][3]);
    }
}

// ============================================================
// Fused reduce + residual + LayerNorm:
//   X = p0 + p1 + xbias;  Y = LN(X + R)*g + b; optional half Yh.
// ============================================================
__global__ __launch_bounds__(256) void resid_ln2(
    const float* __restrict__ p0, const float* __restrict__ p1,
    const float* __restrict__ xbias,
    const float* __restrict__ R,
    const float* __restrict__ g, const float* __restrict__ b,
    float* __restrict__ Y, __half* __restrict__ Yh)
{
    __shared__ float red[8];
    const int row = blockIdx.x;
    const int tid = threadIdx.x;

    float4 a4 = ((const float4*)(p0 + (size_t)row * 1024))[tid];
    float4 b4 = ((const float4*)(p1 + (size_t)row * 1024))[tid];
    float4 xb = ((const float4*)xbias)[tid];
    float4 rv = ((const float4*)(R + (size_t)row * 1024))[tid];
    float v[4] = {a4.x + b4.x + xb.x + rv.x, a4.y + b4.y + xb.y + rv.y,
                  a4.z + b4.z + xb.z + rv.z, a4.w + b4.w + xb.w + rv.w};

    float s = v[0] + v[1] + v[2] + v[3];
#pragma unroll
    for (int o = 16; o; o >>= 1) s += __shfl_xor_sync(0xffffffffu, s, o);
    if ((tid & 31) == 0) red[tid >> 5] = s;
    __syncthreads();
    float mean = 0.f;
#pragma unroll
    for (int w = 0; w < 8; ++w) mean += red[w];
    mean *= (1.0f / 1024.0f);

    float d0 = v[0] - mean, d1 = v[1] - mean, d2 = v[2] - mean, d3 = v[3] - mean;
    float ss = d0 * d0 + d1 * d1 + d2 * d2 + d3 * d3;
#pragma unroll
    for (int o = 16; o; o >>= 1) ss += __shfl_xor_sync(0xffffffffu, ss, o);
    __syncthreads();
    if ((tid & 31) == 0) red[tid >> 5] = ss;
    __syncthreads();
    float var = 0.f;
#pragma unroll
    for (int w = 0; w < 8; ++w) var += red[w];
    var *= (1.0f / 1024.0f);
    const float rstd = rsqrtf(var + 1e-5f);

    float4 gv = ((const float4*)g)[tid];
    float4 bv = ((const float4*)b)[tid];
    float4 o4;
    o4.x = d0 * rstd * gv.x + bv.x;
    o4.y = d1 * rstd * gv.y + bv.y;
    o4.z = d2 * rstd * gv.z + bv.z;
    o4.w = d3 * rstd * gv.w + bv.w;
    ((float4*)(Y + (size_t)row * 1024))[tid] = o4;
    if (Yh) {
        __half2* oh = (__half2*)(Yh + (size_t)row * 1024) + tid * 2;
        oh[0] = __floats2half2_rn(o4.x, o4.y);
        oh[1] = __floats2half2_rn(o4.z, o4.w);
    }
}

// ============================================================
extern "C" void kernel_launch(void* const* d_in, const int* in_sizes, int n_in,
                              void* d_out, int out_size)
{
    (void)in_sizes; (void)n_in; (void)out_size;
    const float* x1  = (const float*)d_in[0];
    const float* x2  = (const float*)d_in[1];
    const float* Wq  = (const float*)d_in[2];
    const float* bq  = (const float*)d_in[3];
    const float* Wk  = (const float*)d_in[4];
    const float* bk  = (const float*)d_in[5];
    const float* Wv  = (const float*)d_in[6];
    const float* bv  = (const float*)d_in[7];
    const float* Wo  = (const float*)d_in[8];
    const float* bo  = (const float*)d_in[9];
    const float* W1  = (const float*)d_in[10];
    const float* b1  = (const float*)d_in[11];
    const float* W2  = (const float*)d_in[12];
    const float* b2  = (const float*)d_in[13];
    const float* g1  = (const float*)d_in[14];
    const float* be1 = (const float*)d_in[15];
    const float* g2  = (const float*)d_in[16];
    const float* be2 = (const float*)d_in[17];
    float* out = (float*)d_out;

    __half *x1h, *x2h, *Wqh, *Wkh, *Wvh, *Woh, *W1h, *W2h;
    __half *Qh, *Kh, *Vh, *Vth, *Ph, *attnh, *hh, *f1h;
    float *hb, *part;
    cudaGetSymbolAddress((void**)&x1h,   g_x1h);
    cudaGetSymbolAddress((void**)&x2h,   g_x2h);
    cudaGetSymbolAddress((void**)&Wqh,   g_Wqh);
    cudaGetSymbolAddress((void**)&Wkh,   g_Wkh);
    cudaGetSymbolAddress((void**)&Wvh,   g_Wvh);
    cudaGetSymbolAddress((void**)&Woh,   g_Woh);
    cudaGetSymbolAddress((void**)&W1h,   g_W1h);
    cudaGetSymbolAddress((void**)&W2h,   g_W2h);
    cudaGetSymbolAddress((void**)&Qh,    g_Qh);
    cudaGetSymbolAddress((void**)&Kh,    g_Kh);
    cudaGetSymbolAddress((void**)&Vh,    g_Vh);
    cudaGetSymbolAddress((void**)&Vth,   g_Vth);
    cudaGetSymbolAddress((void**)&Ph,    g_Ph);
    cudaGetSymbolAddress((void**)&attnh, g_attnh);
    cudaGetSymbolAddress((void**)&hb,    g_h);
    cudaGetSymbolAddress((void**)&hh,    g_hh);
    cudaGetSymbolAddress((void**)&f1h,   g_f1h);
    cudaGetSymbolAddress((void**)&part,  g_part);
    float* part1 = part + (size_t)2048 * 1024;

    cudaFuncSetAttribute(gemm_h,       cudaFuncAttributeMaxDynamicSharedMemorySize, GEMM_SMEM);
    cudaFuncSetAttribute(gemm_qkv,     cudaFuncAttributeMaxDynamicSharedMemorySize, GEMM_SMEM);
    cudaFuncSetAttribute(gemm_attn_sk, cudaFuncAttributeMaxDynamicSharedMemorySize, GEMM_SMEM);
    cudaFuncSetAttribute(gemm_sk,      cudaFuncAttributeMaxDynamicSharedMemorySize, GEMM_SMEM);

    dim3 t256(256);

    // fused input conversion
    {
        ConvSeg cs;
        const float* ins[8]  = {x1, x2, Wq, Wk, Wv, Wo, W1, W2};
        __half* outs[8]      = {x1h, x2h, Wqh, Wkh, Wvh, Woh, W1h, W2h};
        const unsigned n4[8] = {512u * 1024u, 512u * 1024u, 256u * 1024u, 256u * 1024u,
                                256u * 1024u, 256u * 1024u, 1024u * 1024u, 1024u * 1024u};
        unsigned c = 0;
        for (int i = 0; i < 8; ++i) { cs.in[i] = ins[i]; cs.out[i] = outs[i]; cs.cum[i] = c; c += n4[i]; }
        cs.cum[8] = c;
        to_half_multi<<<(c + 255) / 256, t256>>>(cs);
    }

    // merged QKV projections
    {
        QKVArgs q;
        q.A[0] = x1h; q.A[1] = x2h; q.A[2] = x2h;
        q.B[0] = Wqh; q.B[1] = Wkh; q.B[2] = Wvh;
        q.bias[0] = bq; q.bias[1] = bk; q.bias[2] = bv;
        q.C[0] = Qh; q.C[1] = Kh; q.C[2] = Vh;
        gemm_qkv<<<dim3(8, 16, 3), t256, GEMM_SMEM>>>(q);
    }

    // transpose V
    vt_kernel<<<dim3(64, 4, 8), dim3(32, 8)>>>(Vh, Vth);

    // scores per head (half out), softmax in place
    gemm_h<<<dim3(16, 16, 8), t256, GEMM_SMEM>>>(Qh, 128, 1024, Kh, 128, 1024, nullptr,
                                                 nullptr, Ph, (long long)1 << 22, 2048, 128, 0);
    softmax8h<<<4096, t256>>>(Ph);

    // attn = P_h @ Vth_h^T, split-K=2 -> fp32 partials -> half
    gemm_attn_sk<<<dim3(1, 16, 16), t256, GEMM_SMEM>>>(Ph, Vth, part);
    add2half<<<2048, t256>>>(part, part1, attnh);

    // output projection, split-K=2 -> partials; fused reduce+bias+LN
    gemm_sk<<<dim3(8, 16, 2), t256, GEMM_SMEM>>>(attnh, 1024, Woh, 1024, part, 512);
    resid_ln2<<<2048, t256>>>(part, part1, bo, x1, g1, be1, hb, hh);

    // FFN1 (relu, bias)
    gemm_h<<<dim3(32, 16, 1), t256, GEMM_SMEM>>>(hh, 0, 1024, W1h, 0, 1024, b1,
                                                 nullptr, f1h, 0, 4096, 1024, 1);
    // FFN2, split-K=2 -> partials; fused reduce+bias+LN -> out
    gemm_sk<<<dim3(8, 16, 2), t256, GEMM_SMEM>>>(f1h, 4096, W2h, 4096, part, 2048);
    resid_ln2<<<2048, t256>>>(part, part1, b2, hb, g2, be2, out, nullptr);
}

// round 17
// speedup vs baseline: 1.3949x; 1.3949x over previous
#include <cuda_runtime.h>
#include <cuda_fp16.h>
#include <math.h>
#include <stdint.h>

#define E_   1024
#define NH_  8
#define HD_  128
#define BS_  2048

// ---- scratch (device globals; no allocation allowed) ----
__device__ __half g_x1h[BS_ * E_];
__device__ __half g_x2h[BS_ * E_];
__device__ __half g_Wqh[E_ * E_];
__device__ __half g_Wkh[E_ * E_];
__device__ __half g_Wvh[E_ * E_];
__device__ __half g_Woh[E_ * E_];
__device__ __half g_W1h[4 * E_ * E_];
__device__ __half g_W2h[4 * E_ * E_];
__device__ __half g_Qh[BS_ * E_];
__device__ __half g_Kh[BS_ * E_];
__device__ __half g_Vh[BS_ * E_];
__device__ __half g_Vth[NH_ * HD_ * BS_];        // per-head transposed V (half)
__device__ __half g_Ph[(size_t)NH_ * BS_ * BS_]; // half scores -> probs (in place)
__device__ __half g_attnh[BS_ * E_];
__device__ float  g_h[BS_ * E_];
__device__ __half g_hh[BS_ * E_];
__device__ __half g_f1h[BS_ * 4 * E_];
__device__ float  g_part[2 * BS_ * E_];          // split-K partials

// ============================================================
// helpers
// ============================================================
__device__ __forceinline__ uint32_t smem_u32(const void* p) {
    uint32_t a;
    asm("{ .reg .u64 t; cvta.to.shared.u64 t, %1; cvt.u32.u64 %0, t; }" : "=r"(a) : "l"(p));
    return a;
}
__device__ __forceinline__ void cp16(uint32_t dst, const void* src) {
    asm volatile("cp.async.cg.shared.global [%0], [%1], 16;" :: "r"(dst), "l"(src));
}
__device__ __forceinline__ void mbar_init(uint32_t a, uint32_t cnt) {
    asm volatile("mbarrier.init.shared.b64 [%0], %1;" :: "r"(a), "r"(cnt) : "memory");
}
// .noinc: cp-completion performs a REAL arrive (init count covers it).
__device__ __forceinline__ void cp_arrive(uint32_t a) {
    asm volatile("cp.async.mbarrier.arrive.noinc.shared.b64 [%0];" :: "r"(a) : "memory");
}
__device__ __forceinline__ void mbar_arrive(uint32_t a) {
    asm volatile("mbarrier.arrive.shared.b64 _, [%0];" :: "r"(a) : "memory");
}
__device__ __forceinline__ void mbar_wait(uint32_t a, uint32_t parity) {
    asm volatile(
        "{\n\t.reg .pred P;\n\t"
        "WL_%=:\n\t"
        "mbarrier.try_wait.parity.acquire.cta.shared::cta.b64 P, [%0], %1, 0x989680;\n\t"
        "@P bra.uni WD_%=;\n\t"
        "bra.uni WL_%=;\n\t"
        "WD_%=:\n\t}"
        :: "r"(a), "r"(parity) : "memory");
}

__device__ __forceinline__ void mma16(float c[4], uint32_t a0, uint32_t a1,
                                      uint32_t a2, uint32_t a3,
                                      uint32_t b0, uint32_t b1) {
    asm volatile(
        "mma.sync.aligned.m16n8k16.row.col.f32.f16.f16.f32 "
        "{%0,%1,%2,%3}, {%4,%5,%6,%7}, {%8,%9}, {%0,%1,%2,%3};"
        : "+f"(c[0]), "+f"(c[1]), "+f"(c[2]), "+f"(c[3])
        : "r"(a0), "r"(a1), "r"(a2), "r"(a3), "r"(b0), "r"(b1));
}
__device__ __forceinline__ void ldmx4(uint32_t& r0, uint32_t& r1, uint32_t& r2,
                                      uint32_t& r3, uint32_t addr) {
    asm volatile("ldmatrix.sync.aligned.m8n8.x4.shared.b16 {%0,%1,%2,%3}, [%4];"
                 : "=r"(r0), "=r"(r1), "=r"(r2), "=r"(r3) : "r"(addr));
}
__device__ __forceinline__ void ldmx2(uint32_t& r0, uint32_t& r1, uint32_t addr) {
    asm volatile("ldmatrix.sync.aligned.m8n8.x2.shared.b16 {%0,%1}, [%2];"
                 : "=r"(r0), "=r"(r1) : "r"(addr));
}

// ============================================================
// fused multi-tensor fp32 -> fp16 convert (8 segments, one launch)
// ============================================================
struct ConvSeg {
    const float* in[8];
    __half* out[8];
    unsigned cum[9];
};

__global__ __launch_bounds__(256) void to_half_multi(ConvSeg cs)
{
    const unsigned idx = blockIdx.x * 256 + threadIdx.x;
    if (idx >= cs.cum[8]) return;
    int s = 0;
#pragma unroll
    for (int i = 1; i < 8; ++i) s += (idx >= cs.cum[i]);
    const unsigned off = idx - cs.cum[s];
    float4 v = ((const float4*)cs.in[s])[off];
    __half2* o = (__half2*)cs.out[s] + (size_t)off * 2;
    o[0] = __floats2half2_rn(v.x, v.y);
    o[1] = __floats2half2_rn(v.z, v.w);
}

// ============================================================
// fp16 tensor-core NT GEMM core: C = A @ B^T (+bias), opt ReLU
// BM=BN=128, BK=32, 4-stage cp.async ring with per-stage
// full/empty mbarriers (no __syncthreads in the mainloop),
// ldmatrix, 8 warps (2x4), warp tile 64x32, mma m16n8k16.
// ============================================================
#define SROWH 40                         // halves per smem row (32 + 8 pad)
#define STAGE_H (2 * 128 * SROWH)        // halves per stage
#define GEMM_SMEM (4 * STAGE_H * 2)      // bytes (4 stages)

__device__ __forceinline__ void gemm_core(
    const __half* __restrict__ A, int lda,
    const __half* __restrict__ B, int ldb,
    const float* __restrict__ bias,
    float* __restrict__ Cf, __half* __restrict__ Ch, int ldc,
    int K, int relu, int koff, __half* smh)
{
    __shared__ __align__(8) unsigned long long mbars[8]; // full[0..3], empty[4..7]
    const int tid = threadIdx.x;
    const int bm = blockIdx.y * 128, bn = blockIdx.x * 128;
    const uint32_t mb = smem_u32(mbars);

    if (tid == 0) {
#pragma unroll
        for (int s = 0; s < 4; ++s) {
            mbar_init(mb + s * 8, 256);       // full: one cp-completion arrive per thread
            mbar_init(mb + 32 + s * 8, 8);    // empty: one arrive per warp
        }
    }
    __syncthreads();

    const int lrow = tid >> 1;
    const int lc16 = (tid & 1) << 4;
    const __half* gA = A + (size_t)(bm + lrow) * lda + koff + lc16;
    const __half* gB = B + (size_t)(bn + lrow) * ldb + koff + lc16;
    const uint32_t smbase = smem_u32(smh);
    const uint32_t sA0 = smbase + (uint32_t)(lrow * SROWH + lc16) * 2u;
    const uint32_t sB0 = sA0 + 128u * SROWH * 2u;

    const int warp = tid >> 5, lane = tid & 31;
    const int g = lane >> 2, tig = lane & 3;
    const int am = (warp >> 2) * 64;
    const int bnw = (warp & 3) * 32;

    const uint32_t aAddr0 = smbase +
        (uint32_t)(((am + (lane & 15)) * SROWH) + ((lane >> 4) << 3)) * 2u;
    const uint32_t bAddr0 = smbase + 128u * SROWH * 2u +
        (uint32_t)(((bnw + (lane & 7)) * SROWH) + (((lane >> 3) & 1) << 3)) * 2u;

    float acc[4][4][4];
#pragma unroll
    for (int mi = 0; mi < 4; ++mi)
#pragma unroll
        for (int ni = 0; ni < 4; ++ni)
#pragma unroll
            for (int r = 0; r < 4; ++r) acc[mi][ni][r] = 0.f;

    const int NT = K >> 5;

    // prologue: fill stages 0,1,2
#pragma unroll
    for (int s = 0; s < 3; ++s) {
        const uint32_t dA = sA0 + (uint32_t)(s * STAGE_H) * 2u;
        const uint32_t dB = sB0 + (uint32_t)(s * STAGE_H) * 2u;
        const __half* pa = gA + s * 32;
        const __half* pb = gB + s * 32;
        cp16(dA,       pa);     cp16(dA + 16u, pa + 8);
        cp16(dB,       pb);     cp16(dB + 16u, pb + 8);
        cp_arrive(mb + s * 8);
    }

    for (int kt = 0; kt < NT; ++kt) {
        // refill stage (kt+3)&3 with data for kt+3 (stage consumed at kt-1)
        if (kt + 3 < NT) {
            const int sp = (kt + 3) & 3;
            if (kt >= 1) mbar_wait(mb + 32 + sp * 8, ((kt - 1) >> 2) & 1);
            const uint32_t dA = sA0 + (uint32_t)(sp * STAGE_H) * 2u;
            const uint32_t dB = sB0 + (uint32_t)(sp * STAGE_H) * 2u;
            const __half* pa = gA + (kt + 3) * 32;
            const __half* pb = gB + (kt + 3) * 32;
            cp16(dA,       pa);     cp16(dA + 16u, pa + 8);
            cp16(dB,       pb);     cp16(dB + 16u, pb + 8);
            cp_arrive(mb + sp * 8);
        }

        const int s = kt & 3;
        mbar_wait(mb + s * 8, (kt >> 2) & 1);

        const uint32_t stOff = (uint32_t)(s * STAGE_H) * 2u;

#pragma unroll
        for (int k16 = 0; k16 < 2; ++k16) {
            const uint32_t kOff = (uint32_t)(k16 * 16) * 2u;
            uint32_t a[4][4];
#pragma unroll
            for (int mi = 0; mi < 4; ++mi)
                ldmx4(a[mi][0], a[mi][1], a[mi][2], a[mi][3],
                      aAddr0 + stOff + kOff + (uint32_t)(mi * 16 * SROWH) * 2u);
            uint32_t b[4][2];
#pragma unroll
            for (int ni = 0; ni < 4; ++ni)
                ldmx2(b[ni][0], b[ni][1],
                      bAddr0 + stOff + kOff + (uint32_t)(ni * 8 * SROWH) * 2u);
#pragma unroll
            for (int mi = 0; mi < 4; ++mi)
#pragma unroll
                for (int ni = 0; ni < 4; ++ni)
                    mma16(acc[mi][ni], a[mi][0], a[mi][1], a[mi][2], a[mi][3],
                          b[ni][0], b[ni][1]);
        }

        if (lane == 0) mbar_arrive(mb + 32 + s * 8);
    }

#pragma unroll
    for (int mi = 0; mi < 4; ++mi) {
        const int r0 = bm + am + mi * 16 + g;
#pragma unroll
        for (int ni = 0; ni < 4; ++ni) {
            const int col = bn + bnw + ni * 8 + 2 * tig;
            const float bi0 = bias ? bias[col] : 0.f;
            const float bi1 = bias ? bias[col + 1] : 0.f;
            float v0 = acc[mi][ni][0] + bi0, v1 = acc[mi][ni][1] + bi1;
            float v2 = acc[mi][ni][2] + bi0, v3 = acc[mi][ni][3] + bi1;
            if (relu) {
                v0 = fmaxf(v0, 0.f); v1 = fmaxf(v1, 0.f);
                v2 = fmaxf(v2, 0.f); v3 = fmaxf(v3, 0.f);
            }
            if (Cf) {
                float2 p0 = {v0, v1}, p1 = {v2, v3};
                *(float2*)(Cf + (size_t)r0 * ldc + col) = p0;
                *(float2*)(Cf + (size_t)(r0 + 8) * ldc + col) = p1;
            }
            if (Ch) {
                *(__half2*)(Ch + (size_t)r0 * ldc + col) = __floats2half2_rn(v0, v1);
                *(__half2*)(Ch + (size_t)(r0 + 8) * ldc + col) = __floats2half2_rn(v2, v3);
            }
        }
    }
}

// generic wrapper with per-z plane offsets
__global__ __launch_bounds__(256, 2) void gemm_h(
    const __half* __restrict__ A, long long az, int lda,
    const __half* __restrict__ B, long long bz, int ldb,
    const float* __restrict__ bias,
    float* __restrict__ Cf, __half* __restrict__ Ch,
    long long cz, int ldc, int K, int relu)
{
    extern __shared__ __align__(16) __half smh[];
    const int z = blockIdx.z;
    gemm_core(A + (size_t)z * az, lda, B + (size_t)z * bz, ldb, bias,
              Cf ? Cf + (size_t)z * cz : nullptr,
              Ch ? Ch + (size_t)z * cz : nullptr,
              ldc, K, relu, 0, smh);
}

// merged QKV wrapper
struct QKVArgs {
    const __half* A[3];
    const __half* B[3];
    const float* bias[3];
    __half* C[3];
};
__global__ __launch_bounds__(256, 2) void gemm_qkv(QKVArgs q)
{
    extern __shared__ __align__(16) __half smh[];
    const int z = blockIdx.z;
    gemm_core(q.A[z], 1024, q.B[z], 1024, q.bias[z],
              nullptr, q.C[z], 1024, 1024, 0, 0, smh);
}

// attn split-K wrapper: z = head*2 + split. K=2048 split into 2x1024.
__global__ __launch_bounds__(256, 2) void gemm_attn_sk(
    const __half* __restrict__ P, const __half* __restrict__ Vt,
    float* __restrict__ part)
{
    extern __shared__ __align__(16) __half smh[];
    const int head = blockIdx.z >> 1, split = blockIdx.z & 1;
    gemm_core(P + ((size_t)head << 22), 2048,
              Vt + (size_t)head * 128 * 2048, 2048,
              nullptr,
              part + (size_t)split * (2048 * 1024) + head * 128, nullptr,
              1024, 1024, 0, split * 1024, smh);
}

// generic split-K=2 wrapper (N=1024, M=2048): z = split.
__global__ __launch_bounds__(256, 2) void gemm_sk(
    const __half* __restrict__ A, int lda,
    const __half* __restrict__ B, int ldb,
    float* __restrict__ part, int Ksplit)
{
    extern __shared__ __align__(16) __half smh[];
    const int split = blockIdx.z;
    gemm_core(A, lda, B, ldb, nullptr,
              part + (size_t)split * (2048 * 1024), nullptr,
              1024, Ksplit, 0, split * Ksplit, smh);
}

// ============================================================
// partial reduce: out_h = half(p0 + p1)
// ============================================================
__global__ __launch_bounds__(256) void add2half(
    const float* __restrict__ p0, const float* __restrict__ p1,
    __half* __restrict__ out)
{
    const size_t i = (size_t)blockIdx.x * 256 + threadIdx.x;
    float4 a = ((const float4*)p0)[i];
    float4 b = ((const float4*)p1)[i];
    __half2* o = (__half2*)out + i * 2;
    o[0] = __floats2half2_rn(a.x + b.x, a.y + b.y);
    o[1] = __floats2half2_rn(a.z + b.z, a.w + b.w);
}

// ============================================================
// V transpose (half): Vth[h][d][m] = Vh[m][h*128+d]. Grid (64,4,8)
// ============================================================
__global__ void vt_kernel(const __half* __restrict__ V, __half* __restrict__ Vt)
{
    __shared__ __half t[32][34];
    const int m0 = blockIdx.x * 32, d0 = blockIdx.y * 32, h = blockIdx.z;
    const int tx = threadIdx.x, ty = threadIdx.y;
#pragma unroll
    for (int j = 0; j < 32; j += 8)
        t[ty + j][tx] = V[(size_t)(m0 + ty + j) * 1024 + h * 128 + d0 + tx];
    __syncthreads();
    __half* dst = Vt + (size_t)h * 128 * 2048;
#pragma unroll
    for (int j = 0; j < 32; j += 8)
        dst[(size_t)(d0 + ty + j) * 2048 + m0 + tx] = t[tx][ty + j];
}

// ============================================================
// Softmax over the 8 head planes, in place on half scores.
// ============================================================
__global__ __launch_bounds__(256) void softmax8h(__half* __restrict__ P)
{
    const size_t idx = (size_t)blockIdx.x * 256 + threadIdx.x;
    const float scale = 0.08838834764831845f;  // 1/sqrt(128)
    const size_t planeh = (size_t)1 << 22;

    float v[8][4];
#pragma unroll
    for (int h = 0; h < 8; ++h) {
        const __half2* p = (const __half2*)(P + h * planeh) + idx * 2;
        float2 a = __half22float2(p[0]);
        float2 b = __half22float2(p[1]);
        v[h][0] = a.x; v[h][1] = a.y; v[h][2] = b.x; v[h][3] = b.y;
    }

#pragma unroll
    for (int lane = 0; lane < 4; ++lane) {
        float s[8], mx = -1e30f;
#pragma unroll
        for (int h = 0; h < 8; ++h) {
            s[h] = v[h][lane] * scale;
            mx = fmaxf(mx, s[h]);
        }
        float sum = 0.f;
#pragma unroll
        for (int h = 0; h < 8; ++h) { s[h] = expf(s[h] - mx); sum += s[h]; }
        const float inv = 1.0f / sum;
#pragma unroll
        for (int h = 0; h < 8; ++h) v[h][lane] = s[h] * inv;
    }

#pragma unroll
    for (int h = 0; h < 8; ++h) {
        __half2* p = (__half2*)(P + h * planeh) + idx * 2;
        p[0] = __floats2half2_rn(v[h][0], v[h][1]);
        p[1] = __floats2half2_rn(v[h][2], v[h][3]);
    }
}

// ============================================================
// Fused reduce + residual + LayerNorm:
//   X = p0 + p1 + xbias;  Y = LN(X + R)*g + b; optional half Yh.
// ============================================================
__global__ __launch_bounds__(256) void resid_ln2(
    const float* __restrict__ p0, const float* __restrict__ p1,
    const float* __restrict__ xbias,
    const float* __restrict__ R,
    const float* __restrict__ g, const float* __restrict__ b,
    float* __restrict__ Y, __half* __restrict__ Yh)
{
    __shared__ float red[8];
    const int row = blockIdx.x;
    const int tid = threadIdx.x;

    float4 a4 = ((const float4*)(p0 + (size_t)row * 1024))[tid];
    float4 b4 = ((const float4*)(p1 + (size_t)row * 1024))[tid];
    float4 xb = ((const float4*)xbias)[tid];
    float4 rv = ((const float4*)(R + (size_t)row * 1024))[tid];
    float v[4] = {a4.x + b4.x + xb.x + rv.x, a4.y + b4.y + xb.y + rv.y,
                  a4.z + b4.z + xb.z + rv.z, a4.w + b4.w + xb.w + rv.w};

    float s = v[0] + v[1] + v[2] + v[3];
#pragma unroll
    for (int o = 16; o; o >>= 1) s += __shfl_xor_sync(0xffffffffu, s, o);
    if ((tid & 31) == 0) red[tid >> 5] = s;
    __syncthreads();
    float mean = 0.f;
#pragma unroll
    for (int w = 0; w < 8; ++w) mean += red[w];
    mean *= (1.0f / 1024.0f);

    float d0 = v[0] - mean, d1 = v[1] - mean, d2 = v[2] - mean, d3 = v[3] - mean;
    float ss = d0 * d0 + d1 * d1 + d2 * d2 + d3 * d3;
#pragma unroll
    for (int o = 16; o; o >>= 1) ss += __shfl_xor_sync(0xffffffffu, ss, o);
    __syncthreads();
    if ((tid & 31) == 0) red[tid >> 5] = ss;
    __syncthreads();
    float var = 0.f;
#pragma unroll
    for (int w = 0; w < 8; ++w) var += red[w];
    var *= (1.0f / 1024.0f);
    const float rstd = rsqrtf(var + 1e-5f);

    float4 gv = ((const float4*)g)[tid];
    float4 bv = ((const float4*)b)[tid];
    float4 o4;
    o4.x = d0 * rstd * gv.x + bv.x;
    o4.y = d1 * rstd * gv.y + bv.y;
    o4.z = d2 * rstd * gv.z + bv.z;
    o4.w = d3 * rstd * gv.w + bv.w;
    ((float4*)(Y + (size_t)row * 1024))[tid] = o4;
    if (Yh) {
        __half2* oh = (__half2*)(Yh + (size_t)row * 1024) + tid * 2;
        oh[0] = __floats2half2_rn(o4.x, o4.y);
        oh[1] = __floats2half2_rn(o4.z, o4.w);
    }
}

// ============================================================
extern "C" void kernel_launch(void* const* d_in, const int* in_sizes, int n_in,
                              void* d_out, int out_size)
{
    (void)in_sizes; (void)n_in; (void)out_size;
    const float* x1  = (const float*)d_in[0];
    const float* x2  = (const float*)d_in[1];
    const float* Wq  = (const float*)d_in[2];
    const float* bq  = (const float*)d_in[3];
    const float* Wk  = (const float*)d_in[4];
    const float* bk  = (const float*)d_in[5];
    const float* Wv  = (const float*)d_in[6];
    const float* bv  = (const float*)d_in[7];
    const float* Wo  = (const float*)d_in[8];
    const float* bo  = (const float*)d_in[9];
    const float* W1  = (const float*)d_in[10];
    const float* b1  = (const float*)d_in[11];
    const float* W2  = (const float*)d_in[12];
    const float* b2  = (const float*)d_in[13];
    const float* g1  = (const float*)d_in[14];
    const float* be1 = (const float*)d_in[15];
    const float* g2  = (const float*)d_in[16];
    const float* be2 = (const float*)d_in[17];
    float* out = (float*)d_out;

    __half *x1h, *x2h, *Wqh, *Wkh, *Wvh, *Woh, *W1h, *W2h;
    __half *Qh, *Kh, *Vh, *Vth, *Ph, *attnh, *hh, *f1h;
    float *hb, *part;
    cudaGetSymbolAddress((void**)&x1h,   g_x1h);
    cudaGetSymbolAddress((void**)&x2h,   g_x2h);
    cudaGetSymbolAddress((void**)&Wqh,   g_Wqh);
    cudaGetSymbolAddress((void**)&Wkh,   g_Wkh);
    cudaGetSymbolAddress((void**)&Wvh,   g_Wvh);
    cudaGetSymbolAddress((void**)&Woh,   g_Woh);
    cudaGetSymbolAddress((void**)&W1h,   g_W1h);
    cudaGetSymbolAddress((void**)&W2h,   g_W2h);
    cudaGetSymbolAddress((void**)&Qh,    g_Qh);
    cudaGetSymbolAddress((void**)&Kh,    g_Kh);
    cudaGetSymbolAddress((void**)&Vh,    g_Vh);
    cudaGetSymbolAddress((void**)&Vth,   g_Vth);
    cudaGetSymbolAddress((void**)&Ph,    g_Ph);
    cudaGetSymbolAddress((void**)&attnh, g_attnh);
    cudaGetSymbolAddress((void**)&hb,    g_h);
    cudaGetSymbolAddress((void**)&hh,    g_hh);
    cudaGetSymbolAddress((void**)&f1h,   g_f1h);
    cudaGetSymbolAddress((void**)&part,  g_part);
    float* part1 = part + (size_t)2048 * 1024;

    cudaFuncSetAttribute(gemm_h,       cudaFuncAttributeMaxDynamicSharedMemorySize, GEMM_SMEM);
    cudaFuncSetAttribute(gemm_qkv,     cudaFuncAttributeMaxDynamicSharedMemorySize, GEMM_SMEM);
    cudaFuncSetAttribute(gemm_attn_sk, cudaFuncAttributeMaxDynamicSharedMemorySize, GEMM_SMEM);
    cudaFuncSetAttribute(gemm_sk,      cudaFuncAttributeMaxDynamicSharedMemorySize, GEMM_SMEM);

    dim3 t256(256);

    // fused input conversion
    {
        ConvSeg cs;
        const float* ins[8]  = {x1, x2, Wq, Wk, Wv, Wo, W1, W2};
        __half* outs[8]      = {x1h, x2h, Wqh, Wkh, Wvh, Woh, W1h, W2h};
        const unsigned n4[8] = {512u * 1024u, 512u * 1024u, 256u * 1024u, 256u * 1024u,
                                256u * 1024u, 256u * 1024u, 1024u * 1024u, 1024u * 1024u};
        unsigned c = 0;
        for (int i = 0; i < 8; ++i) { cs.in[i] = ins[i]; cs.out[i] = outs[i]; cs.cum[i] = c; c += n4[i]; }
        cs.cum[8] = c;
        to_half_multi<<<(c + 255) / 256, t256>>>(cs);
    }

    // merged QKV projections
    {
        QKVArgs q;
        q.A[0] = x1h; q.A[1] = x2h; q.A[2] = x2h;
        q.B[0] = Wqh; q.B[1] = Wkh; q.B[2] = Wvh;
        q.bias[0] = bq; q.bias[1] = bk; q.bias[2] = bv;
        q.C[0] = Qh; q.C[1] = Kh; q.C[2] = Vh;
        gemm_qkv<<<dim3(8, 16, 3), t256, GEMM_SMEM>>>(q);
    }

    // transpose V
    vt_kernel<<<dim3(64, 4, 8), dim3(32, 8)>>>(Vh, Vth);

    // scores per head (half out), softmax in place
    gemm_h<<<dim3(16, 16, 8), t256, GEMM_SMEM>>>(Qh, 128, 1024, Kh, 128, 1024, nullptr,
                                                 nullptr, Ph, (long long)1 << 22, 2048, 128, 0);
    softmax8h<<<4096, t256>>>(Ph);

    // attn = P_h @ Vth_h^T, split-K=2 -> fp32 partials -> half
    gemm_attn_sk<<<dim3(1, 16, 16), t256, GEMM_SMEM>>>(Ph, Vth, part);
    add2half<<<2048, t256>>>(part, part1, attnh);

    // output projection, split-K=2 -> partials; fused reduce+bias+LN
    gemm_sk<<<dim3(8, 16, 2), t256, GEMM_SMEM>>>(attnh, 1024, Woh, 1024, part, 512);
    resid_ln2<<<2048, t256>>>(part, part1, bo, x1, g1, be1, hb, hh);

    // FFN1 (relu, bias)
    gemm_h<<<dim3(32, 16, 1), t256, GEMM_SMEM>>>(hh, 0, 1024, W1h, 0, 1024, b1,
                                                 nullptr, f1h, 0, 4096, 1024, 1);
    // FFN2, split-K=2 -> partials; fused reduce+bias+LN -> out
    gemm_sk<<<dim3(8, 16, 2), t256, GEMM_SMEM>>>(f1h, 4096, W2h, 4096, part, 2048);
    resid_ln2<<<2048, t256>>>(part, part1, b2, hb, g2, be2, out, nullptr);
}